// round 8
// baseline (speedup 1.0000x reference)
#include <cuda_runtime.h>
#include <cuda_bf16.h>

// CustomStyleLoss: loss = sum over all (row,chunk) of (sum(x-y over 100)/100)^2 / 25
// Fixed shapes: (16,512,50,50) fp32 -> 8192 rows x 25 chunks x 100 elems
//             = 204,800 chunks. Pure HBM-bound single pass over 164 MB.
// Predicted: ~26 us stage-1 (DRAM-roofline) + ~3 us tail => 28-32 us total.
// Note: loss is symmetric in (input, style) -> input-order-robust.

#define NBLOCKS  1184          // 148 SMs * 8 blocks (one full wave, 2048 thr/SM)
#define NTHREADS 256
#define NWARPS   (NTHREADS / 32)
#define TOTWARPS (NBLOCKS * NWARPS)     // 9472, compile-time
#define CHUNK_ELEMS 100                 // BATCH_SIZE
#define CHUNK_F4    (CHUNK_ELEMS / 4)   // 25 float4 per chunk
#define CHUNKS_PER_ROW 25

__device__ float g_partials[NBLOCKS];

__device__ __forceinline__ float diff_sum_f4(const float4 a, const float4 b) {
    return (a.x - b.x) + (a.y - b.y) + (a.z - b.z) + (a.w - b.w);
}

__global__ void __launch_bounds__(NTHREADS)
style_loss_stage1(const float* __restrict__ x, const float* __restrict__ y,
                  int n_chunks)
{
    const int warp  = threadIdx.x >> 5;
    const int lane  = threadIdx.x & 31;
    const int gwarp = blockIdx.x * NWARPS + warp;

    // Lane offset folded into base pointers once; loop-body address math is a
    // single IMAD per load pair (lets ptxas front-batch the 4 LDG.128).
    const float4* __restrict__ x4 = reinterpret_cast<const float4*>(x) + lane;
    const float4* __restrict__ y4 = reinterpret_cast<const float4*>(y) + lane;

    float acc = 0.0f;
    const bool active = (lane < CHUNK_F4);

    // Warp g owns chunk pairs {2g, 2g+1}: 800 contiguous bytes per tensor per
    // iteration, 4 independent LDG.128 per lane (MLP=4).
    int c = 2 * gwarp;

    for (; c + 1 < n_chunks; c += 2 * TOTWARPS) {
        const int b0 = c * CHUNK_F4;            // max ~5.1M, int32-safe
        const int b1 = b0 + CHUNK_F4;
        float v0 = 0.0f, v1 = 0.0f;
        if (active) {
            float4 a0 = x4[b0];
            float4 a1 = x4[b1];
            float4 s0 = y4[b0];
            float4 s1 = y4[b1];
            v0 = diff_sum_f4(a0, s0);
            v1 = diff_sum_f4(a1, s1);
        }
        // two independent shuffle chains (ILP-2 over SHFL latency)
        #pragma unroll
        for (int o = 16; o > 0; o >>= 1) {
            v0 += __shfl_down_sync(0xffffffffu, v0, o);
            v1 += __shfl_down_sync(0xffffffffu, v1, o);
        }
        if (lane == 0) {
            acc = fmaf(v0, v0, acc);
            acc = fmaf(v1, v1, acc);
        }
    }
    // tail: odd leftover chunk (not hit for even n_chunks; kept for safety)
    if (c < n_chunks) {
        const int b0 = c * CHUNK_F4;
        float v0 = 0.0f;
        if (active)
            v0 = diff_sum_f4(x4[b0], y4[b0]);
        #pragma unroll
        for (int o = 16; o > 0; o >>= 1)
            v0 += __shfl_down_sync(0xffffffffu, v0, o);
        if (lane == 0)
            acc = fmaf(v0, v0, acc);
    }

    __shared__ float s[NWARPS];
    if (lane == 0) s[warp] = acc;
    __syncthreads();
    if (threadIdx.x == 0) {
        float t = 0.0f;
        #pragma unroll
        for (int i = 0; i < NWARPS; i++) t += s[i];
        g_partials[blockIdx.x] = t;
    }
}

// Deterministic single-block final reduction; rewrites d_out on every replay.
__global__ void __launch_bounds__(256)
style_loss_stage2(float* __restrict__ out, float scale)
{
    __shared__ float s[256];
    float t = 0.0f;
    for (int i = threadIdx.x; i < NBLOCKS; i += 256)
        t += g_partials[i];
    s[threadIdx.x] = t;
    __syncthreads();
    #pragma unroll
    for (int o = 128; o > 0; o >>= 1) {
        if (threadIdx.x < o) s[threadIdx.x] += s[threadIdx.x + o];
        __syncthreads();
    }
    if (threadIdx.x == 0)
        out[0] = s[0] * scale;
}

extern "C" void kernel_launch(void* const* d_in, const int* in_sizes, int n_in,
                              void* d_out, int out_size)
{
    const float* x = (const float*)d_in[0];   // input
    const float* y = (const float*)d_in[1];   // style
    float* out = (float*)d_out;

    const int n        = in_sizes[0];          // 20,480,000
    const int n_chunks = n / CHUNK_ELEMS;      // 204,800

    // loss = raw_sum / (100^2 * chunks_per_row)
    const float scale = 1.0f / ((float)CHUNK_ELEMS * (float)CHUNK_ELEMS *
                                (float)CHUNKS_PER_ROW);

    style_loss_stage1<<<NBLOCKS, NTHREADS>>>(x, y, n_chunks);
    style_loss_stage2<<<1, 256>>>(out, scale);
}

// round 11
// speedup vs baseline: 1.0091x; 1.0091x over previous
#include <cuda_runtime.h>
#include <cuda_bf16.h>

// CustomStyleLoss: loss = sum over all (row,chunk) of (sum(x-y over 100)/100)^2 / 25
// Fixed shapes: (16,512,50,50) fp32 -> 8192 rows x 25 chunks x 100 elems
//             = 204,800 chunks. Pure HBM-bound single pass over 164 MB.
// R8 measured: stage-1 at DRAM roofline (6.45 TB/s), stage-2 tail = 6.4 us.
// This round: fuse final reduction via last-block-done -> save the 2nd launch.

#define NBLOCKS  1184          // 148 SMs * 8 blocks (one full wave, 2048 thr/SM)
#define NTHREADS 256
#define NWARPS   (NTHREADS / 32)
#define TOTWARPS (NBLOCKS * NWARPS)     // 9472, compile-time
#define CHUNK_ELEMS 100                 // BATCH_SIZE
#define CHUNK_F4    (CHUNK_ELEMS / 4)   // 25 float4 per chunk
#define CHUNKS_PER_ROW 25

__device__ float        g_partials[NBLOCKS];
__device__ unsigned int g_count = 0;    // self-resetting via atomicInc wrap

__device__ __forceinline__ float diff_sum_f4(const float4 a, const float4 b) {
    return (a.x - b.x) + (a.y - b.y) + (a.z - b.z) + (a.w - b.w);
}

__global__ void __launch_bounds__(NTHREADS)
style_loss_fused(const float* __restrict__ x, const float* __restrict__ y,
                 float* __restrict__ out, int n_chunks, float scale)
{
    const int warp  = threadIdx.x >> 5;
    const int lane  = threadIdx.x & 31;
    const int gwarp = blockIdx.x * NWARPS + warp;

    // Lane offset folded into base pointers once; loop-body address math is a
    // single IMAD per load pair (lets ptxas front-batch the 4 LDG.128).
    const float4* __restrict__ x4 = reinterpret_cast<const float4*>(x) + lane;
    const float4* __restrict__ y4 = reinterpret_cast<const float4*>(y) + lane;

    float acc = 0.0f;
    const bool active = (lane < CHUNK_F4);

    // Warp g owns chunk pairs {2g, 2g+1}: 800 contiguous bytes per tensor per
    // iteration, 4 independent LDG.128 per lane (MLP=4).
    int c = 2 * gwarp;

    for (; c + 1 < n_chunks; c += 2 * TOTWARPS) {
        const int b0 = c * CHUNK_F4;            // max ~5.1M, int32-safe
        const int b1 = b0 + CHUNK_F4;
        float v0 = 0.0f, v1 = 0.0f;
        if (active) {
            float4 a0 = x4[b0];
            float4 a1 = x4[b1];
            float4 s0 = y4[b0];
            float4 s1 = y4[b1];
            v0 = diff_sum_f4(a0, s0);
            v1 = diff_sum_f4(a1, s1);
        }
        // two independent shuffle chains (ILP-2 over SHFL latency)
        #pragma unroll
        for (int o = 16; o > 0; o >>= 1) {
            v0 += __shfl_down_sync(0xffffffffu, v0, o);
            v1 += __shfl_down_sync(0xffffffffu, v1, o);
        }
        if (lane == 0) {
            acc = fmaf(v0, v0, acc);
            acc = fmaf(v1, v1, acc);
        }
    }
    // tail: odd leftover chunk (not hit for even n_chunks; kept for safety)
    if (c < n_chunks) {
        const int b0 = c * CHUNK_F4;
        float v0 = 0.0f;
        if (active)
            v0 = diff_sum_f4(x4[b0], y4[b0]);
        #pragma unroll
        for (int o = 16; o > 0; o >>= 1)
            v0 += __shfl_down_sync(0xffffffffu, v0, o);
        if (lane == 0)
            acc = fmaf(v0, v0, acc);
    }

    // ---- block partial ----
    __shared__ float s[NWARPS];
    __shared__ bool  is_last;
    if (lane == 0) s[warp] = acc;
    __syncthreads();
    if (threadIdx.x == 0) {
        float t = 0.0f;
        #pragma unroll
        for (int i = 0; i < NWARPS; i++) t += s[i];
        g_partials[blockIdx.x] = t;
        __threadfence();                         // publish partial before count
        // atomicInc wraps to 0 when old == NBLOCKS-1 -> counter self-resets
        // every launch; graph-replay safe, no init kernel needed.
        unsigned old = atomicInc(&g_count, NBLOCKS - 1);
        is_last = (old == NBLOCKS - 1);
    }
    __syncthreads();

    // ---- last block performs the deterministic final reduction ----
    if (is_last) {
        __shared__ float r[NTHREADS];
        float t = 0.0f;
        for (int i = threadIdx.x; i < NBLOCKS; i += NTHREADS)
            t += g_partials[i];                  // fixed order -> deterministic
        r[threadIdx.x] = t;
        __syncthreads();
        #pragma unroll
        for (int o = NTHREADS / 2; o > 0; o >>= 1) {
            if (threadIdx.x < o) r[threadIdx.x] += r[threadIdx.x + o];
            __syncthreads();
        }
        if (threadIdx.x == 0)
            out[0] = r[0] * scale;
    }
}

extern "C" void kernel_launch(void* const* d_in, const int* in_sizes, int n_in,
                              void* d_out, int out_size)
{
    const float* x = (const float*)d_in[0];   // input
    const float* y = (const float*)d_in[1];   // style
    float* out = (float*)d_out;

    const int n        = in_sizes[0];          // 20,480,000
    const int n_chunks = n / CHUNK_ELEMS;      // 204,800

    // loss = raw_sum / (100^2 * chunks_per_row)
    const float scale = 1.0f / ((float)CHUNK_ELEMS * (float)CHUNK_ELEMS *
                                (float)CHUNKS_PER_ROW);

    style_loss_fused<<<NBLOCKS, NTHREADS>>>(x, y, out, n_chunks, scale);
}

// round 12
// speedup vs baseline: 1.0174x; 1.0082x over previous
#include <cuda_runtime.h>
#include <cuda_bf16.h>

// CustomStyleLoss: loss = sum over (row,chunk) of (sum(x-y over 100)/100)^2 / 25
// Fixed shapes: (16,512,50,50) fp32 -> 204,800 chunks of 100. 164 MB streamed.
// R11 post-mortem: 8 blocks/SM forced regs=32 -> ptxas serialized loads ->
// MLP~1 -> DRAM 69%. This round: 4 blocks/SM (64-reg budget), unroll-4,
// front-batched 8x LDG.128 per lane -> MLP=8.

#define NBLOCKS  592           // 148 SMs * 4 blocks (one wave, 1024 thr/SM)
#define NTHREADS 256
#define NWARPS   (NTHREADS / 32)
#define TOTWARPS (NBLOCKS * NWARPS)     // 4736, compile-time
#define CHUNK_ELEMS 100                 // BATCH_SIZE
#define CHUNK_F4    (CHUNK_ELEMS / 4)   // 25 float4 per chunk
#define CHUNKS_PER_ROW 25

__device__ float        g_partials[NBLOCKS];
__device__ unsigned int g_count = 0;    // self-resetting via atomicInc wrap

__device__ __forceinline__ float diff_sum_f4(const float4 a, const float4 b) {
    return (a.x - b.x) + (a.y - b.y) + (a.z - b.z) + (a.w - b.w);
}

__global__ void __launch_bounds__(NTHREADS, 4)   // min 4 blocks/SM -> <=64 regs
style_loss_fused(const float* __restrict__ x, const float* __restrict__ y,
                 float* __restrict__ out, int n_chunks, float scale)
{
    const int warp  = threadIdx.x >> 5;
    const int lane  = threadIdx.x & 31;
    const int gwarp = blockIdx.x * NWARPS + warp;

    const float4* __restrict__ x4 = reinterpret_cast<const float4*>(x) + lane;
    const float4* __restrict__ y4 = reinterpret_cast<const float4*>(y) + lane;

    float acc = 0.0f;
    const bool active = (lane < CHUNK_F4);

    // Warp owns chunk quads {4q..4q+3}: 1600 contiguous bytes per tensor per
    // iteration; ALL 8 float4 loaded before any arithmetic -> 8 independent
    // LDG.128 in flight (MLP=8).
    const int n_quads = n_chunks >> 2;

    for (int q = gwarp; q < n_quads; q += TOTWARPS) {
        const int b0 = (q << 2) * CHUNK_F4;      // max ~5.1M, int32-safe
        const int b1 = b0 + CHUNK_F4;
        const int b2 = b0 + 2 * CHUNK_F4;
        const int b3 = b0 + 3 * CHUNK_F4;
        float v0 = 0.f, v1 = 0.f, v2 = 0.f, v3 = 0.f;
        if (active) {
            float4 a0 = x4[b0];
            float4 a1 = x4[b1];
            float4 a2 = x4[b2];
            float4 a3 = x4[b3];
            float4 s0 = y4[b0];
            float4 s1 = y4[b1];
            float4 s2 = y4[b2];
            float4 s3 = y4[b3];
            v0 = diff_sum_f4(a0, s0);
            v1 = diff_sum_f4(a1, s1);
            v2 = diff_sum_f4(a2, s2);
            v3 = diff_sum_f4(a3, s3);
        }
        // four interleaved shuffle chains (ILP-4 over SHFL latency)
        #pragma unroll
        for (int o = 16; o > 0; o >>= 1) {
            v0 += __shfl_down_sync(0xffffffffu, v0, o);
            v1 += __shfl_down_sync(0xffffffffu, v1, o);
            v2 += __shfl_down_sync(0xffffffffu, v2, o);
            v3 += __shfl_down_sync(0xffffffffu, v3, o);
        }
        if (lane == 0) {
            acc = fmaf(v0, v0, acc);
            acc = fmaf(v1, v1, acc);
            acc = fmaf(v2, v2, acc);
            acc = fmaf(v3, v3, acc);
        }
    }
    // leftover chunks (n_chunks % 4): one chunk per low-gwarp warp.
    // (n_chunks = 204,800 -> none; kept for generality.)
    const int rem = n_chunks & 3;
    if (gwarp < rem) {
        const int c  = (n_quads << 2) + gwarp;
        const int b0 = c * CHUNK_F4;
        float v0 = 0.0f;
        if (active)
            v0 = diff_sum_f4(x4[b0], y4[b0]);
        #pragma unroll
        for (int o = 16; o > 0; o >>= 1)
            v0 += __shfl_down_sync(0xffffffffu, v0, o);
        if (lane == 0)
            acc = fmaf(v0, v0, acc);
    }

    // ---- block partial ----
    __shared__ float s[NWARPS];
    __shared__ bool  is_last;
    if (lane == 0) s[warp] = acc;
    __syncthreads();
    if (threadIdx.x == 0) {
        float t = 0.0f;
        #pragma unroll
        for (int i = 0; i < NWARPS; i++) t += s[i];
        g_partials[blockIdx.x] = t;
        __threadfence();                         // publish partial before count
        // atomicInc wraps to 0 when old == NBLOCKS-1 -> self-resetting per
        // launch; graph-replay safe, no init kernel.
        unsigned old = atomicInc(&g_count, NBLOCKS - 1);
        is_last = (old == NBLOCKS - 1);
    }
    __syncthreads();

    // ---- last block performs the deterministic final reduction ----
    if (is_last) {
        __shared__ float r[NTHREADS];
        float t = 0.0f;
        for (int i = threadIdx.x; i < NBLOCKS; i += NTHREADS)
            t += g_partials[i];                  // fixed order -> deterministic
        r[threadIdx.x] = t;
        __syncthreads();
        #pragma unroll
        for (int o = NTHREADS / 2; o > 0; o >>= 1) {
            if (threadIdx.x < o) r[threadIdx.x] += r[threadIdx.x + o];
            __syncthreads();
        }
        if (threadIdx.x == 0)
            out[0] = r[0] * scale;
    }
}

extern "C" void kernel_launch(void* const* d_in, const int* in_sizes, int n_in,
                              void* d_out, int out_size)
{
    const float* x = (const float*)d_in[0];   // input
    const float* y = (const float*)d_in[1];   // style
    float* out = (float*)d_out;

    const int n        = in_sizes[0];          // 20,480,000
    const int n_chunks = n / CHUNK_ELEMS;      // 204,800

    // loss = raw_sum / (100^2 * chunks_per_row)
    const float scale = 1.0f / ((float)CHUNK_ELEMS * (float)CHUNK_ELEMS *
                                (float)CHUNKS_PER_ROW);

    style_loss_fused<<<NBLOCKS, NTHREADS>>>(x, y, out, n_chunks, scale);
}